// round 1
// baseline (speedup 1.0000x reference)
#include <cuda_runtime.h>
#include <cuda_bf16.h>
#include <mma.h>
#include <stdint.h>

using namespace nvcuda;

// Problem constants
constexpr int N      = 8192;
constexpr int WORDS  = N / 32;   // 256 bitmask words per row

// ---------------------------------------------------------------------------
// Scratch (static __device__ globals; allocation-free per harness rules)
// ---------------------------------------------------------------------------
__device__ uint32_t       g_bits[(size_t)N * WORDS];   // 8 MB adjacency bitmask (B = edge!=0)
__device__ float          g_dinv[N];
__device__ float          g_ydf[(size_t)N * 128];      // dinv_j * (Y@W), fp32 (for +I diagonal term)
__device__ __nv_bfloat16  g_ydh[(size_t)N * 128];      // hi split
__device__ __nv_bfloat16  g_ydl[(size_t)N * 128];      // lo split
__device__ float          g_h[(size_t)N * 64];         // layer-1 activation
__device__ float          g_rexd[(size_t)N * 128];     // [re | xd] fused activation
__device__ __nv_bfloat16  g_reh[(size_t)N * 64];       // re hi
__device__ __nv_bfloat16  g_rel[(size_t)N * 64];       // re lo

// ---------------------------------------------------------------------------
// 1) Prep: bitmask + degrees + dinv (reads edge_index once, 268 MB)
// ---------------------------------------------------------------------------
__global__ void __launch_bounds__(256) prep_kernel(const int* __restrict__ edge) {
    int row  = blockIdx.x;
    int lane = threadIdx.x & 31;
    int warp = threadIdx.x >> 5;
    __shared__ int wcnt[8];

    const int* erow = edge + (size_t)row * N;
    int cnt = 0;
#pragma unroll 4
    for (int w = 0; w < 32; ++w) {
        int col = warp * 1024 + w * 32 + lane;
        unsigned mask = __ballot_sync(0xFFFFFFFFu, erow[col] != 0);
        if (lane == 0) {
            g_bits[(size_t)row * WORDS + warp * 32 + w] = mask;
            cnt += __popc(mask);
        }
    }
    if (lane == 0) wcnt[warp] = cnt;
    __syncthreads();
    if (threadIdx.x == 0) {
        int deg = 1;  // self loop (+I); note A_hat_ii may be 2 -> handled as B + I everywhere
#pragma unroll
        for (int i = 0; i < 8; ++i) deg += wcnt[i];
        g_dinv[row] = rsqrtf((float)deg);
    }
}

// ---------------------------------------------------------------------------
// 2) Small GEMM: yd = dinv_r * (act @ W); writes fp32 + hi/lo bf16 split
//    act_sel: 0 = external ptr, 1 = g_h, 2 = g_rexd
// ---------------------------------------------------------------------------
__global__ void small_gemm_kernel(const float* __restrict__ act_ext, int act_sel,
                                  int act_ld, int act_c0,
                                  const float* __restrict__ W, int Kin,
                                  int out_ld, int out_c0) {
    const float* act = (act_sel == 1) ? g_h : ((act_sel == 2) ? g_rexd : act_ext);
    int row  = blockIdx.x;
    int Cout = blockDim.x;
    __shared__ float sa[128];
    for (int k = threadIdx.x; k < Kin; k += Cout)
        sa[k] = act[(size_t)row * act_ld + act_c0 + k];
    __syncthreads();

    int c = threadIdx.x;
    float acc = 0.f;
#pragma unroll 8
    for (int k = 0; k < Kin; ++k)
        acc = fmaf(sa[k], W[k * Cout + c], acc);

    float yd = g_dinv[row] * acc;
    int o = row * out_ld + out_c0 + c;
    g_ydf[o] = yd;
    __nv_bfloat16 hi = __float2bfloat16(yd);
    g_ydh[o] = hi;
    g_ydl[o] = __float2bfloat16(yd - __bfloat162float(hi));
}

// ---------------------------------------------------------------------------
// 3) Big adjacency GEMM: out = lrelu(dinv_i*(B@yd + yd_i) + bias)
//    A expanded 0/1 -> bf16 from bitmask in SMEM; yd consumed as hi+lo bf16.
//    dest_sel: 0 = g_h, 1 = g_rexd, 2 = out_ext
//    bias = (c < bsplit) ? bias_a[c] : bias_b[c - bsplit]
// ---------------------------------------------------------------------------
template <int BN>
__global__ void __launch_bounds__(256) big_gcn_kernel(const float* __restrict__ bias_a,
                                                      const float* __restrict__ bias_b,
                                                      int bsplit,
                                                      float* out_ext, int dest_sel) {
    constexpr int BM  = 64;
    constexpr int LDA = 24;        // 16 + 8 pad (mult of 8 for wmma)
    constexpr int LDB = BN + 16;   // mult of 8; rows 16B-aligned for uint4 stores
    constexpr int WN  = BN / 2;    // warp column width (8 warps in 4x2)
    constexpr int NF  = WN / 16;   // b/acc fragments per warp
    constexpr int EPT = BN / 16;   // bf16 elems per thread per B row chunk

    __shared__ alignas(32) __nv_bfloat16 sA[BM * LDA];
    __shared__ alignas(32) __nv_bfloat16 sBh[16 * LDB];
    __shared__ alignas(32) __nv_bfloat16 sBl[16 * LDB];
    __shared__ alignas(32) float sC[BM * BN];

    float* out = (dest_sel == 0) ? g_h : ((dest_sel == 1) ? g_rexd : out_ext);

    int tid  = threadIdx.x;
    int warp = tid >> 5;
    int wr   = warp >> 1;          // 0..3
    int wc   = warp & 1;           // 0..1
    int r0   = blockIdx.x * BM;

    wmma::fragment<wmma::accumulator, 16, 16, 16, float> acc[NF];
#pragma unroll
    for (int j = 0; j < NF; ++j) wmma::fill_fragment(acc[j], 0.f);

    // B staging indices: 16 rows x BN cols, 16 threads per row
    int kr = tid >> 4;
    int cg = (tid & 15) * EPT;
    // A expansion indices: 64 rows x 16 cols, 4 threads per row, 4 cols each
    int ar  = tid >> 2;
    int ac4 = (tid & 3) << 2;

    for (int k0 = 0; k0 < N; k0 += 16) {
        // stage B (hi/lo)
        if constexpr (EPT == 8) {
            *(uint4*)&sBh[kr * LDB + cg] = *(const uint4*)&g_ydh[(size_t)(k0 + kr) * BN + cg];
            *(uint4*)&sBl[kr * LDB + cg] = *(const uint4*)&g_ydl[(size_t)(k0 + kr) * BN + cg];
        } else {
            *(uint2*)&sBh[kr * LDB + cg] = *(const uint2*)&g_ydh[(size_t)(k0 + kr) * BN + cg];
            *(uint2*)&sBl[kr * LDB + cg] = *(const uint2*)&g_ydl[(size_t)(k0 + kr) * BN + cg];
        }
        // expand A bits -> bf16 {0,1}
        uint32_t word = g_bits[(size_t)(r0 + ar) * WORDS + (k0 >> 5)];
        uint32_t w = word >> ((k0 & 16) + ac4);
        uint32_t u0 = ((w & 1u) ? 0x3F80u : 0u) | ((w & 2u) ? 0x3F800000u : 0u);
        uint32_t u1 = ((w & 4u) ? 0x3F80u : 0u) | ((w & 8u) ? 0x3F800000u : 0u);
        *(uint2*)&sA[ar * LDA + ac4] = make_uint2(u0, u1);

        __syncthreads();

        wmma::fragment<wmma::matrix_a, 16, 16, 16, __nv_bfloat16, wmma::row_major> a;
        wmma::load_matrix_sync(a, &sA[(wr * 16) * LDA], LDA);
#pragma unroll
        for (int j = 0; j < NF; ++j) {
            wmma::fragment<wmma::matrix_b, 16, 16, 16, __nv_bfloat16, wmma::row_major> bh, bl;
            wmma::load_matrix_sync(bh, &sBh[wc * WN + j * 16], LDB);
            wmma::load_matrix_sync(bl, &sBl[wc * WN + j * 16], LDB);
            wmma::mma_sync(acc[j], a, bh, acc[j]);
            wmma::mma_sync(acc[j], a, bl, acc[j]);
        }
        __syncthreads();
    }

#pragma unroll
    for (int j = 0; j < NF; ++j)
        wmma::store_matrix_sync(&sC[(wr * 16) * BN + wc * WN + j * 16], acc[j], BN,
                                wmma::mem_row_major);
    __syncthreads();

    for (int e = tid; e < BM * BN; e += 256) {
        int r = e / BN, c = e % BN;
        int gr = r0 + r;
        float b = (c < bsplit) ? bias_a[c] : bias_b[c - bsplit];
        float v = g_dinv[gr] * (sC[e] + g_ydf[gr * BN + c]) + b;  // +I diagonal term
        v = (v > 0.f) ? v : 0.01f * v;                            // leaky relu
        out[(size_t)gr * BN + c] = v;
    }
}

// ---------------------------------------------------------------------------
// 4) Split re (cols 0..63 of g_rexd) into hi/lo bf16 for the recon GEMM
// ---------------------------------------------------------------------------
__global__ void split_re_kernel() {
    int i = blockIdx.x * blockDim.x + threadIdx.x;  // < N*64
    int r = i >> 6, c = i & 63;
    float v = g_rexd[r * 128 + c];
    __nv_bfloat16 hi = __float2bfloat16(v);
    g_reh[i] = hi;
    g_rel[i] = __float2bfloat16(v - __bfloat162float(hi));
}

// ---------------------------------------------------------------------------
// 5) recon = sigmoid(re @ re^T)   (hi/lo split, 3-term: hh + hl + lh)
// ---------------------------------------------------------------------------
__global__ void __launch_bounds__(256) recon_kernel(float* __restrict__ out) {
    constexpr int LD = 72;  // 64 + 8 pad
    __shared__ alignas(32) __nv_bfloat16 smem[4 * 64 * LD];  // 36 KB
    __nv_bfloat16* sAh = smem;
    __nv_bfloat16* sAl = smem + 1 * 64 * LD;
    __nv_bfloat16* sBh = smem + 2 * 64 * LD;
    __nv_bfloat16* sBl = smem + 3 * 64 * LD;

    int tid = threadIdx.x;
    int r0 = blockIdx.y * 64, c0 = blockIdx.x * 64;

    // stage: each thread copies 16 bf16 (2x uint4) per tile
    int lr = tid >> 2, lc = (tid & 3) << 4;
    {
        const uint4* sh = (const uint4*)&g_reh[(size_t)(r0 + lr) * 64 + lc];
        const uint4* sl = (const uint4*)&g_rel[(size_t)(r0 + lr) * 64 + lc];
        uint4* dh = (uint4*)&sAh[lr * LD + lc];
        uint4* dl = (uint4*)&sAl[lr * LD + lc];
        dh[0] = sh[0]; dh[1] = sh[1];
        dl[0] = sl[0]; dl[1] = sl[1];
        const uint4* th = (const uint4*)&g_reh[(size_t)(c0 + lr) * 64 + lc];
        const uint4* tl = (const uint4*)&g_rel[(size_t)(c0 + lr) * 64 + lc];
        uint4* eh = (uint4*)&sBh[lr * LD + lc];
        uint4* el = (uint4*)&sBl[lr * LD + lc];
        eh[0] = th[0]; eh[1] = th[1];
        el[0] = tl[0]; el[1] = tl[1];
    }
    __syncthreads();

    int warp = tid >> 5;
    int wr = warp >> 1, wc = warp & 1;  // 4x2 -> warp tile 16x32

    wmma::fragment<wmma::accumulator, 16, 16, 16, float> acc[2];
    wmma::fill_fragment(acc[0], 0.f);
    wmma::fill_fragment(acc[1], 0.f);

#pragma unroll
    for (int kc = 0; kc < 4; ++kc) {
        int k = kc * 16;
        wmma::fragment<wmma::matrix_a, 16, 16, 16, __nv_bfloat16, wmma::row_major> ah, al;
        wmma::load_matrix_sync(ah, &sAh[(wr * 16) * LD + k], LD);
        wmma::load_matrix_sync(al, &sAl[(wr * 16) * LD + k], LD);
#pragma unroll
        for (int j = 0; j < 2; ++j) {
            int col = wc * 32 + j * 16;
            wmma::fragment<wmma::matrix_b, 16, 16, 16, __nv_bfloat16, wmma::col_major> bh, bl;
            wmma::load_matrix_sync(bh, &sBh[col * LD + k], LD);
            wmma::load_matrix_sync(bl, &sBl[col * LD + k], LD);
            wmma::mma_sync(acc[j], ah, bh, acc[j]);
            wmma::mma_sync(acc[j], ah, bl, acc[j]);
            wmma::mma_sync(acc[j], al, bh, acc[j]);
        }
    }
    __syncthreads();

    float* sC = reinterpret_cast<float*>(smem);  // 16 KB, reuses staging area
#pragma unroll
    for (int j = 0; j < 2; ++j)
        wmma::store_matrix_sync(&sC[(wr * 16) * 64 + wc * 32 + j * 16], acc[j], 64,
                                wmma::mem_row_major);
    __syncthreads();

#pragma unroll
    for (int it = 0; it < 4; ++it) {
        int f4 = tid + it * 256;        // float4 index within 64x64 tile
        int r  = f4 >> 4;
        int c4 = (f4 & 15) << 2;
        float4 s = ((float4*)sC)[f4];
        float4 o;
        o.x = 1.f / (1.f + __expf(-s.x));
        o.y = 1.f / (1.f + __expf(-s.y));
        o.z = 1.f / (1.f + __expf(-s.z));
        o.w = 1.f / (1.f + __expf(-s.w));
        *(float4*)&out[(size_t)(r0 + r) * N + c0 + c4] = o;
    }
}

// ---------------------------------------------------------------------------
// Launch: sequential GCN chain on the default stream (graph-capturable)
// ---------------------------------------------------------------------------
extern "C" void kernel_launch(void* const* d_in, const int* in_sizes, int n_in,
                              void* d_out, int out_size) {
    (void)in_sizes; (void)n_in; (void)out_size;
    const float* x    = (const float*)d_in[0];
    const int*   edge = (const int*)  d_in[1];
    const float* W1   = (const float*)d_in[2];
    const float* b1   = (const float*)d_in[3];
    const float* W2   = (const float*)d_in[4];
    const float* b2   = (const float*)d_in[5];
    const float* We   = (const float*)d_in[6];
    const float* be   = (const float*)d_in[7];
    const float* Wd1  = (const float*)d_in[8];
    const float* bd1  = (const float*)d_in[9];
    const float* Wd2  = (const float*)d_in[10];
    const float* bd2  = (const float*)d_in[11];

    float* out   = (float*)d_out;
    float* recon = out;                           // [N, N]
    float* xout  = out + (size_t)N * N;           // [N, 128]
    float* zout  = xout + (size_t)N * 128;        // [N, 128]

    // adjacency bitmask + dinv
    prep_kernel<<<N, 256>>>(edge);

    // layer 1: h = lrelu(nadj @ (x@W1) + b1)           [N,64]
    small_gemm_kernel<<<N, 64>>>(x, 0, 128, 0, W1, 128, 64, 0);
    big_gcn_kernel<64><<<N / 64, 256>>>(b1, b1, 64, nullptr, 0);           // -> g_h

    // layer 2: z = lrelu(nadj @ (h@W2) + b2)           [N,128] -> d_out z region
    small_gemm_kernel<<<N, 128>>>(nullptr, 1, 64, 0, W2, 64, 128, 0);
    big_gcn_kernel<128><<<N / 64, 256>>>(b2, b2, 128, zout, 2);

    // layers 3+4 fused: [re | xd] = lrelu(nadj @ (z@[We|Wd1]) + [be|bd1])  [N,128]
    small_gemm_kernel<<<N, 64>>>(zout, 0, 128, 0, We,  128, 128, 0);
    small_gemm_kernel<<<N, 64>>>(zout, 0, 128, 0, Wd1, 128, 128, 64);
    big_gcn_kernel<128><<<N / 64, 256>>>(be, bd1, 64, nullptr, 1);         // -> g_rexd

    // split re into hi/lo for the recon GEMM
    split_re_kernel<<<(N * 64) / 256, 256>>>();

    // layer 5: x_out = lrelu(nadj @ (xd@Wd2) + bd2)    [N,128] -> d_out x region
    small_gemm_kernel<<<N, 128>>>(nullptr, 2, 128, 64, Wd2, 64, 128, 0);
    big_gcn_kernel<128><<<N / 64, 256>>>(bd2, bd2, 128, xout, 2);

    // recon_edge = sigmoid(re @ re^T)                  [N,N]
    recon_kernel<<<dim3(128, 128), 256>>>(recon);
}

// round 2
// speedup vs baseline: 1.8223x; 1.8223x over previous
#include <cuda_runtime.h>
#include <cuda_bf16.h>
#include <mma.h>
#include <stdint.h>

using namespace nvcuda;

constexpr int N     = 8192;
constexpr int WORDS = N / 32;

// ---------------------------------------------------------------------------
// Scratch
// ---------------------------------------------------------------------------
__device__ uint32_t       g_bits[(size_t)N * WORDS];   // 8 MB adjacency bitmask
__device__ float          g_dinv[N];
__device__ float          g_ydf[(size_t)N * 128];      // dinv_j * (Y@W) fp32
__device__ __nv_bfloat16  g_ydh[(size_t)N * 128];      // hi split
__device__ __nv_bfloat16  g_ydl[(size_t)N * 128];      // lo split
__device__ float          g_h[(size_t)N * 64];
__device__ float          g_rexd[(size_t)N * 128];     // [re | xd]
__device__ __nv_bfloat16  g_reh[(size_t)N * 64];
__device__ __nv_bfloat16  g_rel[(size_t)N * 64];

// ---------------------------------------------------------------------------
// cp.async helper (8-byte)
// ---------------------------------------------------------------------------
__device__ __forceinline__ void cp8(void* smem_dst, const void* gsrc) {
    uint32_t d = (uint32_t)__cvta_generic_to_shared(smem_dst);
    asm volatile("cp.async.ca.shared.global [%0], [%1], 8;\n" :: "r"(d), "l"(gsrc));
}
__device__ __forceinline__ void cp_commit() {
    asm volatile("cp.async.commit_group;\n" ::: "memory");
}
__device__ __forceinline__ void cp_wait0() {
    asm volatile("cp.async.wait_group 0;\n" ::: "memory");
}

// ---------------------------------------------------------------------------
// 1) Prep: bitmask + dinv
// ---------------------------------------------------------------------------
__global__ void __launch_bounds__(256) prep_kernel(const int* __restrict__ edge) {
    int row  = blockIdx.x;
    int lane = threadIdx.x & 31;
    int warp = threadIdx.x >> 5;
    __shared__ int wcnt[8];

    const int* erow = edge + (size_t)row * N;
    int cnt = 0;
#pragma unroll 4
    for (int w = 0; w < 32; ++w) {
        int col = warp * 1024 + w * 32 + lane;
        unsigned mask = __ballot_sync(0xFFFFFFFFu, erow[col] != 0);
        if (lane == 0) {
            g_bits[(size_t)row * WORDS + warp * 32 + w] = mask;
            cnt += __popc(mask);
        }
    }
    if (lane == 0) wcnt[warp] = cnt;
    __syncthreads();
    if (threadIdx.x == 0) {
        int deg = 1;  // self loop
#pragma unroll
        for (int i = 0; i < 8; ++i) deg += wcnt[i];
        g_dinv[row] = rsqrtf((float)deg);
    }
}

// ---------------------------------------------------------------------------
// 2) small GEMM v2: yd = dinv_r * (act @ W); W staged in SMEM once per block.
//    512 threads, 16 rows per block, grid = 512.
// ---------------------------------------------------------------------------
__global__ void __launch_bounds__(512) small_gemm2(const float* __restrict__ act_ext,
                                                   int act_sel, int act_ld, int act_c0,
                                                   const float* __restrict__ W,
                                                   int Kin, int Cout,
                                                   int out_ld, int out_c0) {
    const float* act = (act_sel == 1) ? g_h : ((act_sel == 2) ? g_rexd : act_ext);
    __shared__ float sW[8192];       // Kin*Cout <= 8192 floats (32 KB)
    __shared__ float sact[1024];     // R*Kin <= 1024 floats

    int tid = threadIdx.x;
    int KC2 = Kin * Cout;
    for (int i = tid; i < KC2; i += 512) sW[i] = W[i];

    int c  = tid % Cout;
    int ry = tid / Cout;
    int R  = 512 / Cout;
    int rbase = blockIdx.x * 16;

    for (int it = 0; it < 16; it += R) {
        __syncthreads();  // sW ready (first iter) / sact reuse safe
        for (int j = tid; j < R * Kin; j += 512) {
            int r = j / Kin, k = j - r * Kin;
            sact[j] = act[(size_t)(rbase + it + r) * act_ld + act_c0 + k];
        }
        __syncthreads();

        int row = rbase + it + ry;
        float acc = 0.f;
#pragma unroll 8
        for (int k = 0; k < Kin; ++k)
            acc = fmaf(sact[ry * Kin + k], sW[k * Cout + c], acc);

        float yd = g_dinv[row] * acc;
        int o = row * out_ld + out_c0 + c;
        g_ydf[o] = yd;
        __nv_bfloat16 hi = __float2bfloat16(yd);
        g_ydh[o] = hi;
        g_ydl[o] = __float2bfloat16(yd - __bfloat162float(hi));
    }
}

// ---------------------------------------------------------------------------
// 3) big adjacency GEMM v2: out = lrelu(dinv_i*(B@yd + yd_i) + bias)
//    BMxBN=BMx64 tile, KC=32 double-buffered (cp.async B, register-expand A).
//    8 warps, warp tile (BM/4)x32.
// ---------------------------------------------------------------------------
template <int BM>
__global__ void __launch_bounds__(256, 2) big_gcn2(const float* __restrict__ bias_a,
                                                   const float* __restrict__ bias_b,
                                                   int bsplit, int PW,
                                                   float* out_ext, int dest_sel,
                                                   int out_ld) {
    constexpr int KC  = 32;
    constexpr int LDA = 40;
    constexpr int LDB = 72;
    constexpr int NC  = N / KC;
    constexpr int ASZ = BM * LDA;   // elems per A buffer
    constexpr int BSZ = KC * LDB;   // elems per B buffer (one of h/l)
    constexpr int WM  = BM / 4;     // warp tile rows
    constexpr int FM  = WM / 16;    // a/acc frags per warp (rows)
    constexpr int TPR = 256 / BM;   // threads per A row
    constexpr int EB  = 32 / TPR;   // bits expanded per thread

    constexpr size_t SME = 2 * ASZ + 4 * BSZ;  // > BM*64*2 (fp32 sC alias) for both BM
    __shared__ __align__(16) __nv_bfloat16 smem[SME];
    __nv_bfloat16* sA  = smem;                 // [2][ASZ]
    __nv_bfloat16* sBh = smem + 2 * ASZ;       // [2][BSZ]
    __nv_bfloat16* sBl = smem + 2 * ASZ + 2 * BSZ;

    float* out = (dest_sel == 0) ? g_h : ((dest_sel == 1) ? g_rexd : out_ext);

    int tid  = threadIdx.x;
    int warp = tid >> 5;
    int wr   = warp >> 1;   // 0..3
    int wc   = warp & 1;    // 0..1
    int r0   = blockIdx.x * BM;
    int c0   = blockIdx.y * 64;

    // A expansion mapping
    int arow = tid / TPR;
    int bit0 = (tid % TPR) * EB;

    wmma::fragment<wmma::accumulator, 16, 16, 16, float> acc[FM][2];
#pragma unroll
    for (int fm = 0; fm < FM; ++fm)
#pragma unroll
        for (int fn = 0; fn < 2; ++fn) wmma::fill_fragment(acc[fm][fn], 0.f);

    auto fetchB = [&](int ch, int buf) {
        int k0 = ch * KC;
#pragma unroll
        for (int s = tid; s < 512; s += 256) {
            int row = s >> 4, seg = s & 15;
            size_t g = (size_t)(k0 + row) * PW + c0 + seg * 4;
            cp8(&sBh[buf * BSZ + row * LDB + seg * 4], &g_ydh[g]);
            cp8(&sBl[buf * BSZ + row * LDB + seg * 4], &g_ydl[g]);
        }
        cp_commit();
    };
    auto expandA = [&](int ch, int buf) {
        uint32_t w = g_bits[(size_t)(r0 + arow) * WORDS + ch] >> bit0;
        uint32_t u[EB / 2];
#pragma unroll
        for (int i = 0; i < EB / 2; ++i)
            u[i] = (((w >> (2 * i)) & 1u) ? 0x3F80u : 0u) |
                   (((w >> (2 * i + 1)) & 1u) ? 0x3F800000u : 0u);
        uint4* dst = (uint4*)&sA[buf * ASZ + arow * LDA + bit0];
        dst[0] = make_uint4(u[0], u[1], u[2], u[3]);
        if (EB == 16) dst[1] = make_uint4(u[4], u[5], u[6], u[7]);
    };

    int buf = 0;
    fetchB(0, 0);
    expandA(0, 0);
    cp_wait0();
    __syncthreads();

    for (int ch = 0; ch < NC; ++ch) {
        int nbuf = buf ^ 1;
        if (ch + 1 < NC) {
            fetchB(ch + 1, nbuf);
            expandA(ch + 1, nbuf);
        }
        // compute on buf
#pragma unroll
        for (int ks = 0; ks < 2; ++ks) {
            wmma::fragment<wmma::matrix_a, 16, 16, 16, __nv_bfloat16, wmma::row_major> a[FM];
#pragma unroll
            for (int fm = 0; fm < FM; ++fm)
                wmma::load_matrix_sync(a[fm],
                    &sA[buf * ASZ + (wr * WM + fm * 16) * LDA + ks * 16], LDA);
#pragma unroll
            for (int fn = 0; fn < 2; ++fn) {
                wmma::fragment<wmma::matrix_b, 16, 16, 16, __nv_bfloat16, wmma::row_major> bh, bl;
                int bcol = wc * 32 + fn * 16;
                wmma::load_matrix_sync(bh, &sBh[buf * BSZ + (ks * 16) * LDB + bcol], LDB);
                wmma::load_matrix_sync(bl, &sBl[buf * BSZ + (ks * 16) * LDB + bcol], LDB);
#pragma unroll
                for (int fm = 0; fm < FM; ++fm) {
                    wmma::mma_sync(acc[fm][fn], a[fm], bh, acc[fm][fn]);
                    wmma::mma_sync(acc[fm][fn], a[fm], bl, acc[fm][fn]);
                }
            }
        }
        if (ch + 1 < NC) cp_wait0();
        __syncthreads();
        buf = nbuf;
    }

    // epilogue: accs -> sC (aliases smem) -> global with dinv/+I/bias/lrelu
    float* sC = (float*)smem;
#pragma unroll
    for (int fm = 0; fm < FM; ++fm)
#pragma unroll
        for (int fn = 0; fn < 2; ++fn)
            wmma::store_matrix_sync(&sC[(wr * WM + fm * 16) * 64 + wc * 32 + fn * 16],
                                    acc[fm][fn], 64, wmma::mem_row_major);
    __syncthreads();

    bool left = (c0 < bsplit);  // whole 64-col block is on one side (bsplit mult of 64)
    const float* bias = left ? bias_a : bias_b;
    int boff = left ? c0 : c0 - bsplit;

    for (int idx = tid; idx < BM * 16; idx += 256) {
        int r  = idx >> 4;
        int c4 = (idx & 15) * 4;
        int gr = r0 + r;
        float di = g_dinv[gr];
        float4 s = *(float4*)&sC[r * 64 + c4];
        float4 yd = *(const float4*)&g_ydf[(size_t)gr * PW + c0 + c4];
        float4 o;
        o.x = di * (s.x + yd.x) + bias[boff + c4 + 0];
        o.y = di * (s.y + yd.y) + bias[boff + c4 + 1];
        o.z = di * (s.z + yd.z) + bias[boff + c4 + 2];
        o.w = di * (s.w + yd.w) + bias[boff + c4 + 3];
        o.x = (o.x > 0.f) ? o.x : 0.01f * o.x;
        o.y = (o.y > 0.f) ? o.y : 0.01f * o.y;
        o.z = (o.z > 0.f) ? o.z : 0.01f * o.z;
        o.w = (o.w > 0.f) ? o.w : 0.01f * o.w;
        *(float4*)&out[(size_t)gr * out_ld + c0 + c4] = o;
    }
}

// ---------------------------------------------------------------------------
// 4) split re into hi/lo
// ---------------------------------------------------------------------------
__global__ void split_re_kernel() {
    int i = blockIdx.x * blockDim.x + threadIdx.x;
    int r = i >> 6, c = i & 63;
    float v = g_rexd[r * 128 + c];
    __nv_bfloat16 hi = __float2bfloat16(v);
    g_reh[i] = hi;
    g_rel[i] = __float2bfloat16(v - __bfloat162float(hi));
}

// ---------------------------------------------------------------------------
// 5) recon = sigmoid(re @ re^T), symmetric: compute upper triangle, write both
// ---------------------------------------------------------------------------
__global__ void __launch_bounds__(256) recon_kernel(float* __restrict__ out) {
    if (blockIdx.x < blockIdx.y) return;  // only bx >= by (upper triangle)

    constexpr int LD  = 72;
    constexpr int LDC = 68;
    __shared__ alignas(32) __nv_bfloat16 smem[4 * 64 * LD];
    __nv_bfloat16* sAh = smem;
    __nv_bfloat16* sAl = smem + 1 * 64 * LD;
    __nv_bfloat16* sBh = smem + 2 * 64 * LD;
    __nv_bfloat16* sBl = smem + 3 * 64 * LD;

    int tid = threadIdx.x;
    int r0 = blockIdx.y * 64, c0 = blockIdx.x * 64;

    int lr = tid >> 2, lc = (tid & 3) << 4;
    {
        const uint4* sh = (const uint4*)&g_reh[(size_t)(r0 + lr) * 64 + lc];
        const uint4* sl = (const uint4*)&g_rel[(size_t)(r0 + lr) * 64 + lc];
        uint4* dh = (uint4*)&sAh[lr * LD + lc];
        uint4* dl = (uint4*)&sAl[lr * LD + lc];
        dh[0] = sh[0]; dh[1] = sh[1];
        dl[0] = sl[0]; dl[1] = sl[1];
        const uint4* th = (const uint4*)&g_reh[(size_t)(c0 + lr) * 64 + lc];
        const uint4* tl = (const uint4*)&g_rel[(size_t)(c0 + lr) * 64 + lc];
        uint4* eh = (uint4*)&sBh[lr * LD + lc];
        uint4* el = (uint4*)&sBl[lr * LD + lc];
        eh[0] = th[0]; eh[1] = th[1];
        el[0] = tl[0]; el[1] = tl[1];
    }
    __syncthreads();

    int warp = tid >> 5;
    int wr = warp >> 1, wc = warp & 1;

    wmma::fragment<wmma::accumulator, 16, 16, 16, float> acc[2];
    wmma::fill_fragment(acc[0], 0.f);
    wmma::fill_fragment(acc[1], 0.f);

#pragma unroll
    for (int kc = 0; kc < 4; ++kc) {
        int k = kc * 16;
        wmma::fragment<wmma::matrix_a, 16, 16, 16, __nv_bfloat16, wmma::row_major> ah, al;
        wmma::load_matrix_sync(ah, &sAh[(wr * 16) * LD + k], LD);
        wmma::load_matrix_sync(al, &sAl[(wr * 16) * LD + k], LD);
#pragma unroll
        for (int j = 0; j < 2; ++j) {
            int col = wc * 32 + j * 16;
            wmma::fragment<wmma::matrix_b, 16, 16, 16, __nv_bfloat16, wmma::col_major> bh, bl;
            wmma::load_matrix_sync(bh, &sBh[col * LD + k], LD);
            wmma::load_matrix_sync(bl, &sBl[col * LD + k], LD);
            wmma::mma_sync(acc[j], ah, bh, acc[j]);
            wmma::mma_sync(acc[j], ah, bl, acc[j]);
            wmma::mma_sync(acc[j], al, bh, acc[j]);
        }
    }
    __syncthreads();

    float* sC = reinterpret_cast<float*>(smem);  // 64 x LDC
#pragma unroll
    for (int j = 0; j < 2; ++j)
        wmma::store_matrix_sync(&sC[(wr * 16) * LDC + wc * 32 + j * 16], acc[j], LDC,
                                wmma::mem_row_major);
    __syncthreads();

    // direct tile (r0, c0)
#pragma unroll
    for (int it = 0; it < 4; ++it) {
        int f4 = tid + it * 256;
        int r  = f4 >> 4;
        int c4 = (f4 & 15) << 2;
        float4 o;
        o.x = 1.f / (1.f + __expf(-sC[r * LDC + c4 + 0]));
        o.y = 1.f / (1.f + __expf(-sC[r * LDC + c4 + 1]));
        o.z = 1.f / (1.f + __expf(-sC[r * LDC + c4 + 2]));
        o.w = 1.f / (1.f + __expf(-sC[r * LDC + c4 + 3]));
        *(float4*)&out[(size_t)(r0 + r) * N + c0 + c4] = o;
    }
    // transposed tile (c0, r0)
    if (blockIdx.x != blockIdx.y) {
#pragma unroll
        for (int it = 0; it < 4; ++it) {
            int f4 = tid + it * 256;
            int r  = f4 >> 4;                 // row in transposed tile
            int c4 = (f4 & 15) << 2;
            float4 o;
            o.x = 1.f / (1.f + __expf(-sC[(c4 + 0) * LDC + r]));
            o.y = 1.f / (1.f + __expf(-sC[(c4 + 1) * LDC + r]));
            o.z = 1.f / (1.f + __expf(-sC[(c4 + 2) * LDC + r]));
            o.w = 1.f / (1.f + __expf(-sC[(c4 + 3) * LDC + r]));
            *(float4*)&out[(size_t)(c0 + r) * N + r0 + c4] = o;
        }
    }
}

// ---------------------------------------------------------------------------
// Launch chain
// ---------------------------------------------------------------------------
extern "C" void kernel_launch(void* const* d_in, const int* in_sizes, int n_in,
                              void* d_out, int out_size) {
    (void)in_sizes; (void)n_in; (void)out_size;
    const float* x    = (const float*)d_in[0];
    const int*   edge = (const int*)  d_in[1];
    const float* W1   = (const float*)d_in[2];
    const float* b1   = (const float*)d_in[3];
    const float* W2   = (const float*)d_in[4];
    const float* b2   = (const float*)d_in[5];
    const float* We   = (const float*)d_in[6];
    const float* be   = (const float*)d_in[7];
    const float* Wd1  = (const float*)d_in[8];
    const float* bd1  = (const float*)d_in[9];
    const float* Wd2  = (const float*)d_in[10];
    const float* bd2  = (const float*)d_in[11];

    float* out   = (float*)d_out;
    float* recon = out;
    float* xout  = out + (size_t)N * N;
    float* zout  = xout + (size_t)N * 128;

    prep_kernel<<<N, 256>>>(edge);

    // layer 1: h = lrelu(nadj @ (x@W1) + b1)   [N,64]
    small_gemm2<<<512, 512>>>(x, 0, 128, 0, W1, 128, 64, 64, 0);
    big_gcn2<64><<<dim3(128, 1), 256>>>(b1, b1, 64, 64, nullptr, 0, 64);

    // layer 2: z = lrelu(nadj @ (h@W2) + b2)   [N,128]
    small_gemm2<<<512, 512>>>(nullptr, 1, 64, 0, W2, 64, 128, 128, 0);
    big_gcn2<128><<<dim3(64, 2), 256>>>(b2, b2, 128, 128, zout, 2, 128);

    // layers 3+4 fused: [re | xd]
    small_gemm2<<<512, 512>>>(zout, 0, 128, 0, We,  128, 64, 128, 0);
    small_gemm2<<<512, 512>>>(zout, 0, 128, 0, Wd1, 128, 64, 128, 64);
    big_gcn2<128><<<dim3(64, 2), 256>>>(be, bd1, 64, 128, nullptr, 1, 128);

    split_re_kernel<<<(N * 64) / 256, 256>>>();

    // layer 5: x_out = lrelu(nadj @ (xd@Wd2) + bd2)  [N,128]
    small_gemm2<<<512, 512>>>(nullptr, 2, 128, 64, Wd2, 64, 128, 128, 0);
    big_gcn2<128><<<dim3(64, 2), 256>>>(bd2, bd2, 128, 128, xout, 2, 128);

    // recon = sigmoid(re @ re^T)
    recon_kernel<<<dim3(128, 128), 256>>>(recon);
}